// round 1
// baseline (speedup 1.0000x reference)
#include <cuda_runtime.h>

#define NN 50000
#define EE 800000
#define DD 128

// ---------------- scratch (static device globals; no allocation) ----------
__device__ float g_h[NN * DD];        // hidden activations after layer 0
__device__ float g_agg[NN * DD];      // aggregation output per layer
__device__ int   g_csr_src[EE];
__device__ float g_csr_coef[EE];
__device__ int   g_deg[NN];
__device__ int   g_off[NN + 1];
__device__ int   g_cur[NN];
__device__ float g_dinv[NN];
__device__ int   g_is64;

// ---------------- dtype detection: int64 vs int32 edge_index --------------
// If int64 (values in [0,50000)), every odd 32-bit word of the first 1024
// pairs is 0. If int32, odd words are random indices (virtually never all 0).
__global__ void k_detect(const int* __restrict__ raw) {
    __shared__ int found;
    if (threadIdx.x == 0) found = 0;
    __syncthreads();
    for (int i = threadIdx.x; i < 2048; i += blockDim.x) {
        if (raw[2 * i + 1] != 0) found = 1;   // benign race, same value
    }
    __syncthreads();
    if (threadIdx.x == 0) g_is64 = found ? 0 : 1;
}

__device__ __forceinline__ void load_edge(const void* raw, int e, int is64,
                                          int& s, int& d) {
    if (is64) {
        const long long* p = (const long long*)raw;
        s = (int)p[e];
        d = (int)p[EE + e];
    } else {
        const int* p = (const int*)raw;
        s = p[e];
        d = p[EE + e];
    }
}

// ---------------- prologue: degree, dinv, scan, CSR ------------------------
__global__ void k_init() {
    int i = blockIdx.x * blockDim.x + threadIdx.x;
    if (i < NN) { g_deg[i] = 0; g_cur[i] = 0; }
}

__global__ void k_deg(const void* __restrict__ raw) {
    int e = blockIdx.x * blockDim.x + threadIdx.x;
    if (e >= EE) return;
    int is64 = g_is64;
    int s, d;
    load_edge(raw, e, is64, s, d);
    atomicAdd(&g_deg[d], 1);
}

__global__ void k_dinv() {
    int i = blockIdx.x * blockDim.x + threadIdx.x;
    if (i < NN) g_dinv[i] = rsqrtf((float)g_deg[i] + 1.0f);  // +1 self-loop
}

// single-block exclusive scan of g_deg -> g_off (N=50000, 1024 threads)
__global__ void k_scan() {
    const int T = 1024;
    const int ITEMS = (NN + T - 1) / T;  // 49
    __shared__ int sm[T];
    int t = threadIdx.x;
    int base = t * ITEMS;
    int sum = 0;
    for (int j = 0; j < ITEMS; ++j) {
        int idx = base + j;
        if (idx < NN) sum += g_deg[idx];
    }
    sm[t] = sum;
    __syncthreads();
    // Hillis-Steele inclusive scan
    for (int dstep = 1; dstep < T; dstep <<= 1) {
        int v = (t >= dstep) ? sm[t - dstep] : 0;
        __syncthreads();
        sm[t] += v;
        __syncthreads();
    }
    int run = sm[t] - sum;  // exclusive prefix for this chunk
    for (int j = 0; j < ITEMS; ++j) {
        int idx = base + j;
        if (idx < NN) {
            g_off[idx] = run;
            run += g_deg[idx];
        }
    }
    if (t == T - 1) g_off[NN] = sm[T - 1];
}

__global__ void k_csr(const void* __restrict__ raw) {
    int e = blockIdx.x * blockDim.x + threadIdx.x;
    if (e >= EE) return;
    int is64 = g_is64;
    int s, d;
    load_edge(raw, e, is64, s, d);
    int p = g_off[d] + atomicAdd(&g_cur[d], 1);
    g_csr_src[p]  = s;
    g_csr_coef[p] = g_dinv[s] * g_dinv[d];
}

// ---------------- aggregation: warp per destination node -------------------
// acc = dinv[i]^2 * x[i] + sum_e coef[e] * x[src[e]]
__global__ void k_agg(const float* __restrict__ xext, int use_internal) {
    int gw   = (blockIdx.x * blockDim.x + threadIdx.x) >> 5;
    int lane = threadIdx.x & 31;
    if (gw >= NN) return;
    const float* __restrict__ x = use_internal ? g_h : xext;

    float di = g_dinv[gw];
    float sc = di * di;
    float4 a = ((const float4*)(x + (size_t)gw * DD))[lane];
    float4 acc = make_float4(a.x * sc, a.y * sc, a.z * sc, a.w * sc);

    int beg = g_off[gw];
    int end = g_off[gw + 1];
    for (int e0 = beg; e0 < end; e0 += 32) {
        int m = end - e0;
        if (m > 32) m = 32;
        int   s  = 0;
        float cf = 0.0f;
        if (lane < m) {
            s  = g_csr_src[e0 + lane];
            cf = g_csr_coef[e0 + lane];
        }
        #pragma unroll 4
        for (int j = 0; j < m; ++j) {
            int   sj = __shfl_sync(0xffffffffu, s, j);
            float cj = __shfl_sync(0xffffffffu, cf, j);
            float4 v = ((const float4*)(x + (size_t)sj * DD))[lane];
            acc.x += v.x * cj;
            acc.y += v.y * cj;
            acc.z += v.z * cj;
            acc.w += v.w * cj;
        }
    }
    ((float4*)(g_agg + (size_t)gw * DD))[lane] = acc;
}

// ---------------- GEMM + bias + ReLU: out = relu(g_agg @ W + b) ------------
// Block: 256 threads (8 warps), 64 rows/block, 8 rows/warp.
// W streamed through 32KB smem in two 64-row K-phases.
__global__ void __launch_bounds__(256, 2)
k_gemm(const float* __restrict__ Wg, const float* __restrict__ bg,
       float* __restrict__ outext, int write_internal) {
    __shared__ float Wsm[64 * DD];  // 32 KB
    int tid  = threadIdx.x;
    int lane = tid & 31;
    int wid  = tid >> 5;
    int rowBase = blockIdx.x * 64 + wid * 8;

    const float* __restrict__ A = g_agg;
    float* __restrict__ outp = write_internal ? g_h : outext;

    // load 8 rows of A into registers (4 cols per lane per row)
    float xr[8][4];
    #pragma unroll
    for (int r = 0; r < 8; ++r) {
        int row = rowBase + r;
        if (row < NN) {
            float4 v = ((const float4*)(A + (size_t)row * DD))[lane];
            xr[r][0] = v.x; xr[r][1] = v.y; xr[r][2] = v.z; xr[r][3] = v.w;
        } else {
            xr[r][0] = xr[r][1] = xr[r][2] = xr[r][3] = 0.0f;
        }
    }

    float4 acc[8];
    #pragma unroll
    for (int r = 0; r < 8; ++r) acc[r] = make_float4(0.f, 0.f, 0.f, 0.f);

    for (int ph = 0; ph < 2; ++ph) {
        __syncthreads();
        // stage 64 rows of W into smem (8 float4 per thread)
        const float4* Wg4  = (const float4*)(Wg + (size_t)ph * 64 * DD);
        float4*       Wsm4 = (float4*)Wsm;
        #pragma unroll
        for (int i = 0; i < 8; ++i) Wsm4[i * 256 + tid] = Wg4[i * 256 + tid];
        __syncthreads();

        #pragma unroll 4
        for (int k4 = 0; k4 < 16; ++k4) {
            int srcLane = ph * 16 + k4;
            #pragma unroll
            for (int c = 0; c < 4; ++c) {
                float4 w = ((const float4*)Wsm)[(k4 * 4 + c) * 32 + lane];
                #pragma unroll
                for (int r = 0; r < 8; ++r) {
                    float xv = __shfl_sync(0xffffffffu, xr[r][c], srcLane);
                    acc[r].x += xv * w.x;
                    acc[r].y += xv * w.y;
                    acc[r].z += xv * w.z;
                    acc[r].w += xv * w.w;
                }
            }
        }
    }

    float4 bb = ((const float4*)bg)[lane];
    #pragma unroll
    for (int r = 0; r < 8; ++r) {
        int row = rowBase + r;
        if (row < NN) {
            float4 o;
            o.x = fmaxf(acc[r].x + bb.x, 0.0f);
            o.y = fmaxf(acc[r].y + bb.y, 0.0f);
            o.z = fmaxf(acc[r].z + bb.z, 0.0f);
            o.w = fmaxf(acc[r].w + bb.w, 0.0f);
            ((float4*)(outp + (size_t)row * DD))[lane] = o;
        }
    }
}

// ---------------- launch ----------------------------------------------------
extern "C" void kernel_launch(void* const* d_in, const int* in_sizes, int n_in,
                              void* d_out, int out_size) {
    const float* x  = (const float*)d_in[0];
    const void*  ei = d_in[1];
    const float* W  = (const float*)d_in[2];
    const float* b  = (const float*)d_in[3];
    float* out = (float*)d_out;

    k_detect<<<1, 256>>>((const int*)ei);
    k_init<<<(NN + 255) / 256, 256>>>();
    k_deg<<<(EE + 255) / 256, 256>>>(ei);
    k_dinv<<<(NN + 255) / 256, 256>>>();
    k_scan<<<1, 1024>>>();
    k_csr<<<(EE + 255) / 256, 256>>>(ei);

    int aggGrid  = (NN * 32 + 255) / 256;
    int gemmGrid = (NN + 63) / 64;

    // layer 0: agg(x) -> g_agg; gemm -> g_h
    k_agg<<<aggGrid, 256>>>(x, 0);
    k_gemm<<<gemmGrid, 256>>>(W, b, out, 1);

    // layer 1: agg(g_h) -> g_agg; gemm -> d_out
    k_agg<<<aggGrid, 256>>>(x, 1);
    k_gemm<<<gemmGrid, 256>>>(W + DD * DD, b + DD, out, 0);
}

// round 3
// speedup vs baseline: 1.0539x; 1.0539x over previous
#include <cuda_runtime.h>
#include <cuda_bf16.h>
#include <cstdint>

#define NN 50000
#define EE 800000
#define DD 128
#define TILES ((NN + 127) / 128)   // 391

// ---------------- scratch (static device globals; no allocation) ----------
__device__ float g_h[NN * DD];        // hidden activations after layer 0
__device__ float g_agg[NN * DD];      // aggregation output per layer
__device__ int   g_csr_src[EE];
__device__ float g_csr_coef[EE];
__device__ int   g_deg[NN];
__device__ int   g_off[NN + 1];
__device__ int   g_cur[NN];
__device__ float g_dinv[NN];
__device__ int   g_is64;
// B = W (k-major) packed in mma.m16n8k16 fragment order, bf16 hi/lo:
// uint32 index = (((layer*8 + ks)*16 + nt)*64 + lane*2 + reg)
__device__ uint32_t g_bp_hi[2 * 8 * 16 * 64];
__device__ uint32_t g_bp_lo[2 * 8 * 16 * 64];

// ---------------- dtype detection + init ----------------------------------
__global__ void k_init(const int* __restrict__ raw) {
    int i = blockIdx.x * blockDim.x + threadIdx.x;
    if (i < NN) { g_deg[i] = 0; g_cur[i] = 0; }
    if (blockIdx.x == 0) {
        __shared__ int found;
        if (threadIdx.x == 0) found = 0;
        __syncthreads();
        for (int j = threadIdx.x; j < 2048; j += blockDim.x)
            if (raw[2 * j + 1] != 0) found = 1;
        __syncthreads();
        if (threadIdx.x == 0) g_is64 = found ? 0 : 1;
    }
}

__device__ __forceinline__ void load_edge(const void* raw, int e, int is64,
                                          int& s, int& d) {
    if (is64) {
        const long long* p = (const long long*)raw;
        s = (int)p[e];
        d = (int)p[EE + e];
    } else {
        const int* p = (const int*)raw;
        s = p[e];
        d = p[EE + e];
    }
}

__global__ void k_deg(const void* __restrict__ raw) {
    int e = blockIdx.x * blockDim.x + threadIdx.x;
    if (e >= EE) return;
    int is64 = g_is64;
    int s, d;
    load_edge(raw, e, is64, s, d);
    atomicAdd(&g_deg[d], 1);
}

// single-block scan of g_deg -> g_off; also computes g_dinv
__global__ void k_scan() {
    const int T = 1024;
    const int ITEMS = (NN + T - 1) / T;  // 49
    __shared__ int sm[T];
    int t = threadIdx.x;
    int base = t * ITEMS;
    int sum = 0;
    for (int j = 0; j < ITEMS; ++j) {
        int idx = base + j;
        if (idx < NN) sum += g_deg[idx];
    }
    sm[t] = sum;
    __syncthreads();
    for (int dstep = 1; dstep < T; dstep <<= 1) {
        int v = (t >= dstep) ? sm[t - dstep] : 0;
        __syncthreads();
        sm[t] += v;
        __syncthreads();
    }
    int run = sm[t] - sum;
    for (int j = 0; j < ITEMS; ++j) {
        int idx = base + j;
        if (idx < NN) {
            int dg = g_deg[idx];
            g_off[idx] = run;
            g_dinv[idx] = rsqrtf((float)dg + 1.0f);
            run += dg;
        }
    }
    if (t == T - 1) g_off[NN] = sm[T - 1];
}

__global__ void k_csr(const void* __restrict__ raw) {
    int e = blockIdx.x * blockDim.x + threadIdx.x;
    if (e >= EE) return;
    int is64 = g_is64;
    int s, d;
    load_edge(raw, e, is64, s, d);
    int p = g_off[d] + atomicAdd(&g_cur[d], 1);
    g_csr_src[p]  = s;
    g_csr_coef[p] = g_dinv[s] * g_dinv[d];
}

// ---------------- W -> mma fragment pack (bf16 hi/lo) ----------------------
// mma.m16n8k16 B fragment (col-major K x N=8): thread lane holds
//   reg r (0,1), half i (0,1): B[k = ks*16 + r*8 + (lane%4)*2 + i][n = nt*8 + lane/4]
__global__ void k_wt(const float* __restrict__ W) {
    int idx = blockIdx.x * blockDim.x + threadIdx.x;
    if (idx >= 2 * DD * DD) return;
    int l = idx >> 14;
    int r = idx & 16383;
    int k = r >> 7;    // K index (in-dim)
    int n = r & 127;   // N index (out-dim)
    float v = W[l * DD * DD + k * DD + n];
    __nv_bfloat16 h = __float2bfloat16(v);
    __nv_bfloat16 lo = __float2bfloat16(v - __bfloat162float(h));
    int ks  = k >> 4;
    int kk  = k & 15;
    int reg = kk >> 3;
    int k8  = kk & 7;
    int lane = ((n & 7) << 2) | (k8 >> 1);
    int i    = k8 & 1;
    int nt   = n >> 3;
    size_t u32i = ((((size_t)l * 8 + ks) * 16 + nt) * 64) + (size_t)lane * 2 + reg;
    ((unsigned short*)g_bp_hi)[u32i * 2 + i] = __bfloat16_as_ushort(h);
    ((unsigned short*)g_bp_lo)[u32i * 2 + i] = __bfloat16_as_ushort(lo);
}

// ---------------- aggregation: warp per destination node -------------------
__global__ void k_agg(const float* __restrict__ xext, int use_internal) {
    int gw   = (blockIdx.x * blockDim.x + threadIdx.x) >> 5;
    int lane = threadIdx.x & 31;
    if (gw >= NN) return;
    const float* __restrict__ x = use_internal ? g_h : xext;

    float di = g_dinv[gw];
    float sc = di * di;
    float4 a = ((const float4*)(x + (size_t)gw * DD))[lane];
    float4 acc = make_float4(a.x * sc, a.y * sc, a.z * sc, a.w * sc);

    int beg = g_off[gw];
    int end = g_off[gw + 1];
    for (int e0 = beg; e0 < end; e0 += 32) {
        int m = end - e0;
        if (m > 32) m = 32;
        int   s  = 0;
        float cf = 0.0f;
        if (lane < m) {
            s  = g_csr_src[e0 + lane];
            cf = g_csr_coef[e0 + lane];
        }
        #pragma unroll 4
        for (int j = 0; j < m; ++j) {
            int   sj = __shfl_sync(0xffffffffu, s, j);
            float cj = __shfl_sync(0xffffffffu, cf, j);
            float4 v = ((const float4*)(x + (size_t)sj * DD))[lane];
            acc.x += v.x * cj;
            acc.y += v.y * cj;
            acc.z += v.z * cj;
            acc.w += v.w * cj;
        }
    }
    ((float4*)(g_agg + (size_t)gw * DD))[lane] = acc;
}

// ---------------- mma.sync GEMM: out = relu(g_agg @ W + b), bf16x3 ---------
__device__ __forceinline__ void mma16816(float* d, const uint32_t* a,
                                         const uint32_t b0, const uint32_t b1) {
    asm volatile(
        "mma.sync.aligned.m16n8k16.row.col.f32.bf16.bf16.f32 "
        "{%0,%1,%2,%3}, {%4,%5,%6,%7}, {%8,%9}, {%0,%1,%2,%3};"
        : "+f"(d[0]), "+f"(d[1]), "+f"(d[2]), "+f"(d[3])
        : "r"(a[0]), "r"(a[1]), "r"(a[2]), "r"(a[3]), "r"(b0), "r"(b1));
}

__device__ __forceinline__ uint32_t pack_hi(float2 v) {
    __nv_bfloat162 h = __floats2bfloat162_rn(v.x, v.y);
    return *(uint32_t*)&h;
}
__device__ __forceinline__ uint32_t pack_lo(float2 v) {
    __nv_bfloat16 h0 = __float2bfloat16(v.x);
    __nv_bfloat16 h1 = __float2bfloat16(v.y);
    __nv_bfloat162 l = __floats2bfloat162_rn(v.x - __bfloat162float(h0),
                                             v.y - __bfloat162float(h1));
    return *(uint32_t*)&l;
}

__global__ void __launch_bounds__(256)
k_gemm_mma(const float* __restrict__ bg, float* __restrict__ outext,
           int layer, int write_internal) {
    int tid  = threadIdx.x;
    int lane = tid & 31;
    int wid  = tid >> 5;
    int mbase = blockIdx.x * 128 + (wid & 3) * 32;  // warp's 32 rows
    int nbase = (wid >> 2) * 64;                    // warp's 64 cols (0 or 64)

    const float* __restrict__ A = g_agg;
    float* __restrict__ outp = write_internal ? g_h : outext;

    int qrow = lane >> 2;          // 0..7
    int qcol = (lane & 3) * 2;     // 0,2,4,6

    float acc[2][8][4];
    #pragma unroll
    for (int mt = 0; mt < 2; ++mt)
        #pragma unroll
        for (int nt = 0; nt < 8; ++nt)
            #pragma unroll
            for (int j = 0; j < 4; ++j) acc[mt][nt][j] = 0.0f;

    const uint2* __restrict__ bhiP = (const uint2*)g_bp_hi;
    const uint2* __restrict__ bloP = (const uint2*)g_bp_lo;

    #pragma unroll 2
    for (int ks = 0; ks < 8; ++ks) {
        // ---- A fragments (fp32 -> bf16 hi/lo) ----
        uint32_t ahi[2][4], alo[2][4];
        #pragma unroll
        for (int mt = 0; mt < 2; ++mt) {
            int r0 = mbase + mt * 16 + qrow;
            int r1 = r0 + 8;
            int r0c = (r0 < NN) ? r0 : (NN - 1);
            int r1c = (r1 < NN) ? r1 : (NN - 1);
            const float2* p0 = (const float2*)(A + (size_t)r0c * DD + ks * 16 + qcol);
            const float2* p1 = (const float2*)(A + (size_t)r1c * DD + ks * 16 + qcol);
            float2 x0 = p0[0];
            float2 x1 = p1[0];
            float2 x2 = p0[4];   // +8 floats
            float2 x3 = p1[4];
            ahi[mt][0] = pack_hi(x0); alo[mt][0] = pack_lo(x0);
            ahi[mt][1] = pack_hi(x1); alo[mt][1] = pack_lo(x1);
            ahi[mt][2] = pack_hi(x2); alo[mt][2] = pack_lo(x2);
            ahi[mt][3] = pack_hi(x3); alo[mt][3] = pack_lo(x3);
        }
        // ---- B fragments (pre-packed, contiguous per warp) ----
        int bbase = (((layer * 8 + ks) * 16 + (nbase >> 3)) * 32) + lane;
        uint2 bh[8], bl[8];
        #pragma unroll
        for (int nt = 0; nt < 8; ++nt) {
            bh[nt] = bhiP[bbase + nt * 32];
            bl[nt] = bloP[bbase + nt * 32];
        }
        // ---- 48 HMMA ----
        #pragma unroll
        for (int mt = 0; mt < 2; ++mt)
            #pragma unroll
            for (int nt = 0; nt < 8; ++nt) {
                mma16816(acc[mt][nt], ahi[mt], bh[nt].x, bh[nt].y);
                mma16816(acc[mt][nt], alo[mt], bh[nt].x, bh[nt].y);
                mma16816(acc[mt][nt], ahi[mt], bl[nt].x, bl[nt].y);
            }
    }

    // ---- epilogue: bias + relu + store ----
    #pragma unroll
    for (int nt = 0; nt < 8; ++nt) {
        int col = nbase + nt * 8 + qcol;
        float2 bb = *(const float2*)(bg + col);
        #pragma unroll
        for (int mt = 0; mt < 2; ++mt) {
            int r0 = mbase + mt * 16 + qrow;
            int r1 = r0 + 8;
            if (r0 < NN) {
                float2 o0;
                o0.x = fmaxf(acc[mt][nt][0] + bb.x, 0.0f);
                o0.y = fmaxf(acc[mt][nt][1] + bb.y, 0.0f);
                *(float2*)(outp + (size_t)r0 * DD + col) = o0;
            }
            if (r1 < NN) {
                float2 o1;
                o1.x = fmaxf(acc[mt][nt][2] + bb.x, 0.0f);
                o1.y = fmaxf(acc[mt][nt][3] + bb.y, 0.0f);
                *(float2*)(outp + (size_t)r1 * DD + col) = o1;
            }
        }
    }
}

// ---------------- launch ----------------------------------------------------
extern "C" void kernel_launch(void* const* d_in, const int* in_sizes, int n_in,
                              void* d_out, int out_size) {
    const float* x  = (const float*)d_in[0];
    const void*  ei = d_in[1];
    const float* W  = (const float*)d_in[2];
    const float* b  = (const float*)d_in[3];
    float* out = (float*)d_out;

    k_init<<<(NN + 255) / 256, 256>>>((const int*)ei);
    k_deg<<<(EE + 255) / 256, 256>>>(ei);
    k_scan<<<1, 1024>>>();
    k_csr<<<(EE + 255) / 256, 256>>>(ei);
    k_wt<<<(2 * DD * DD + 255) / 256, 256>>>(W);

    int aggGrid = (NN * 32 + 255) / 256;

    // layer 0
    k_agg<<<aggGrid, 256>>>(x, 0);
    k_gemm_mma<<<TILES, 256>>>(b, out, 0, 1);

    // layer 1
    k_agg<<<aggGrid, 256>>>(x, 1);
    k_gemm_mma<<<TILES, 256>>>(b + DD, out, 1, 0);
}